// round 17
// baseline (speedup 1.0000x reference)
#include <cuda_runtime.h>

#define N_NODES 100000
#define IN_DIM  512
#define OUT_DIM 16
#define N_EDGES 3200000

#define SB 1024                                   // scan block size
#define NBLK ((N_NODES + SB - 1) / SB)            // 98 scan blocks

// GEMM tiling
#define KT      32                                // K-tile
#define NTILES  (IN_DIM / KT)                     // 16
#define TROWS   256                               // rows per block
#define GT      256                               // gemm threads per block
#define XSTRIDE 36                                // staged row stride (floats)
#define XBUF    (TROWS * XSTRIDE)                 // floats per buffer
#define W_SMEM_BYTES  (IN_DIM * 16 * 4)           // 32 KB
#define GEMM_SMEM (W_SMEM_BYTES + 2 * XBUF * 4)   // 106496 B -> 2 blocks/SM

// Scratch (allocation-free rule: __device__ globals).
__device__ int   g_is64;                  // 1 if edge_index buffer is int64
__device__ int   g_cnt[N_NODES];          // in-degree (edges only, no self loop)
__device__ int   g_cur[N_NODES];          // scatter cursors
__device__ int   g_off[N_NODES];          // exclusive prefix of g_cnt
__device__ int   g_blksum[NBLK];          // per-block totals
__device__ int   g_sorted_src[N_EDGES];   // src ids grouped by dst
__device__ __align__(16) float g_feat[N_NODES * OUT_DIM]; // rsqrt(deg)*(x@W)

// ---------------------------------------------------------------------------
// K1: zero counters + dtype detection (thread 0)
// ---------------------------------------------------------------------------
__global__ void init_kernel(const int* __restrict__ ei32) {
    int i = blockIdx.x * blockDim.x + threadIdx.x;
    if (i < N_NODES) { g_cnt[i] = 0; g_cur[i] = 0; }
    if (i == 0) {
        int zeros = 0;
        for (int k = 0; k < 128; ++k) zeros += (ei32[2 * k + 1] == 0);
        g_is64 = (zeros > 64) ? 1 : 0;
    }
}

// ---------------------------------------------------------------------------
// K2: in-degree count, 4 edges per thread, vectorized dst loads
// ---------------------------------------------------------------------------
__global__ void count_kernel(const void* __restrict__ eiv) {
    int q = blockIdx.x * blockDim.x + threadIdx.x;     // quad index
    int e0 = q * 4;
    if (e0 >= N_EDGES) return;
    int d[4];
    if (g_is64) {
        const longlong2* dd = (const longlong2*)((const long long*)eiv + N_EDGES);
        longlong2 a = dd[q * 2];
        longlong2 b = dd[q * 2 + 1];
        d[0] = (int)a.x; d[1] = (int)a.y; d[2] = (int)b.x; d[3] = (int)b.y;
    } else {
        const int4* dd = (const int4*)((const int*)eiv + N_EDGES);
        int4 a = dd[q];
        d[0] = a.x; d[1] = a.y; d[2] = a.z; d[3] = a.w;
    }
#pragma unroll
    for (int k = 0; k < 4; ++k)
        if ((unsigned)d[k] < N_NODES) atomicAdd(&g_cnt[d[k]], 1);
}

// ---------------------------------------------------------------------------
// K3a: per-block scan (1024-chunk, smem Hillis-Steele), local-exclusive out
// ---------------------------------------------------------------------------
__global__ void __launch_bounds__(SB)
scan1_kernel() {
    __shared__ int s[SB];
    int t = threadIdx.x;
    int i = blockIdx.x * SB + t;
    int v = (i < N_NODES) ? g_cnt[i] : 0;
    s[t] = v;
    __syncthreads();
#pragma unroll
    for (int off = 1; off < SB; off <<= 1) {
        int u = (t >= off) ? s[t - off] : 0;
        __syncthreads();
        s[t] += u;
        __syncthreads();
    }
    if (i < N_NODES) g_off[i] = s[t] - v;       // local exclusive
    if (t == SB - 1) g_blksum[blockIdx.x] = s[t];
}

// ---------------------------------------------------------------------------
// K3b: add block base; cooperative load of block sums, then smem sum
// ---------------------------------------------------------------------------
__global__ void __launch_bounds__(SB)
scan23_kernel() {
    __shared__ int sums[NBLK];
    __shared__ int base;
    int t = threadIdx.x;
    if (t < NBLK) sums[t] = (t < (int)blockIdx.x) ? g_blksum[t] : 0;
    __syncthreads();
    if (t == 0) {
        int run = 0;
#pragma unroll 7
        for (int k = 0; k < NBLK; ++k) run += sums[k];
        base = run;
    }
    __syncthreads();
    int i = blockIdx.x * SB + t;
    if (i < N_NODES) g_off[i] += base;
}

// ---------------------------------------------------------------------------
// K4: fused GEMM + scale, X staged through smem (coalesced cp.async tiles).
//     256 threads, 1 row/thread: 16 warps/SM (R16 was latency-bound at 8
//     warps/SM, occ 10.7%, nothing saturated). W broadcast LDS.128 = 1 wf.
// ---------------------------------------------------------------------------
__device__ __forceinline__ void ffma2(unsigned long long& d,
                                      unsigned long long a,
                                      unsigned long long b) {
    asm("fma.rn.f32x2 %0, %1, %2, %0;" : "+l"(d) : "l"(a), "l"(b));
}

__device__ __forceinline__ unsigned long long pack2(float v) {
    unsigned long long r;
    asm("mov.b64 %0, {%1, %1};" : "=l"(r) : "f"(v));
    return r;
}

__device__ __forceinline__ void copy_tile_async(const float* __restrict__ x,
                                                float* __restrict__ dst,
                                                int rowBase, int t, int tid) {
#pragma unroll
    for (int i = 0; i < 8; ++i) {
        int f  = tid + i * GT;           // float4 id in tile (2048 total)
        int r  = f >> 3;                 // tile row
        int c4 = f & 7;                  // float4 column
        int gr = rowBase + r;
        if (gr >= N_NODES) gr = N_NODES - 1;           // clamp (dup row)
        const float* s = x + (size_t)gr * IN_DIM + t * KT + c4 * 4;
        float* d = dst + r * XSTRIDE + c4 * 4;
        unsigned int da = (unsigned int)__cvta_generic_to_shared(d);
        asm volatile("cp.async.cg.shared.global [%0], [%1], 16;"
                     :: "r"(da), "l"(s));
    }
    asm volatile("cp.async.commit_group;");
}

__global__ void __launch_bounds__(GT)
gemm_scale_kernel(const float* __restrict__ x,
                  const float* __restrict__ W) {
    extern __shared__ unsigned char smem[];
    ulonglong2* Ws = (ulonglong2*)smem;                 // [IN_DIM*4], 32KB
    float* xs = (float*)(smem + W_SMEM_BYTES);          // [2][TROWS][XSTRIDE]

    int tid = threadIdx.x;
    int rowBase = blockIdx.x * TROWS;

    // W staging (plain LDG+STS) overlapped with first tile cp.async
    const ulonglong2* W4 = (const ulonglong2*)W;
    for (int i = tid; i < IN_DIM * 4; i += GT) Ws[i] = W4[i];

    copy_tile_async(x, xs, rowBase, 0, tid);

    unsigned long long acc[8];
#pragma unroll
    for (int j = 0; j < 8; ++j) acc[j] = 0ull;

    for (int t = 0; t < NTILES; ++t) {
        if (t + 1 < NTILES)
            copy_tile_async(x, xs + ((t + 1) & 1) * XBUF, rowBase, t + 1, tid);
        else
            asm volatile("cp.async.commit_group;");     // dummy group
        asm volatile("cp.async.wait_group 1;");
        __syncthreads();                                // tile t + W visible

        const float* xr = xs + (t & 1) * XBUF + tid * XSTRIDE;

#pragma unroll
        for (int k8 = 0; k8 < KT / 8; ++k8) {
            float4 a0 = *(const float4*)(xr + k8 * 8);
            float4 a1 = *(const float4*)(xr + k8 * 8 + 4);
            float xa[8] = {a0.x, a0.y, a0.z, a0.w, a1.x, a1.y, a1.z, a1.w};
#pragma unroll
            for (int kk = 0; kk < 8; ++kk) {
                int kb = (t * KT + k8 * 8 + kk) * 4;
                ulonglong2 w0 = Ws[kb];
                ulonglong2 w1 = Ws[kb + 1];
                ulonglong2 w2 = Ws[kb + 2];
                ulonglong2 w3 = Ws[kb + 3];
                unsigned long long x2 = pack2(xa[kk]);
                ffma2(acc[0], x2, w0.x);
                ffma2(acc[1], x2, w0.y);
                ffma2(acc[2], x2, w1.x);
                ffma2(acc[3], x2, w1.y);
                ffma2(acc[4], x2, w2.x);
                ffma2(acc[5], x2, w2.y);
                ffma2(acc[6], x2, w3.x);
                ffma2(acc[7], x2, w3.y);
            }
        }
        __syncthreads();                                // done with buffer
    }

    int row = rowBase + tid;
    if (row < N_NODES) {
        float dinv = rsqrtf((float)(g_cnt[row] + 1));
        float vals[16];
#pragma unroll
        for (int j = 0; j < 8; ++j) {
            float2 p = *(float2*)&acc[j];
            vals[2 * j]     = p.x * dinv;
            vals[2 * j + 1] = p.y * dinv;
        }
        float4* gp = (float4*)(g_feat + (size_t)row * OUT_DIM);
#pragma unroll
        for (int q = 0; q < 4; ++q)
            gp[q] = make_float4(vals[4 * q], vals[4 * q + 1],
                                vals[4 * q + 2], vals[4 * q + 3]);
    }
}

// ---------------------------------------------------------------------------
// K5: counting-sort scatter: group src ids by dst (reads edges directly)
// ---------------------------------------------------------------------------
__global__ void sort_scatter_kernel(const void* __restrict__ eiv) {
    int e = blockIdx.x * blockDim.x + threadIdx.x;
    if (e >= N_EDGES) return;
    int s, d;
    if (g_is64) {
        const long long* ei = (const long long*)eiv;
        s = (int)ei[e];
        d = (int)ei[e + N_EDGES];
    } else {
        const int* ei = (const int*)eiv;
        s = ei[e];
        d = ei[e + N_EDGES];
    }
    if ((unsigned)s >= N_NODES) s = 0;          // defensive
    if ((unsigned)d >= N_NODES) return;         // defensive
    int p = g_off[d] + atomicAdd(&g_cur[d], 1);
    if ((unsigned)p < N_EDGES)                  // defensive
        g_sorted_src[p] = s;
}

// ---------------------------------------------------------------------------
// K6: gather + self-loop + dinv + bias. One warp per node, 2 edges per iter
//     (16 lanes = one contiguous 64B g_feat row each).
// ---------------------------------------------------------------------------
__global__ void __launch_bounds__(256)
gather_kernel(const float* __restrict__ b, float* __restrict__ out) {
    int warp = (blockIdx.x * blockDim.x + threadIdx.x) >> 5;
    if (warp >= N_NODES) return;
    int lane = threadIdx.x & 31;
    int half = lane >> 4;        // 0 or 1: which edge of the pair
    int sub  = lane & 15;        // feature index

    int cnt   = g_cnt[warp];
    int start = g_off[warp];

    float acc = 0.0f;
    for (int j = half; j < cnt; j += 2) {
        int s = g_sorted_src[start + j];
        acc += g_feat[(size_t)s * OUT_DIM + sub];
    }
    acc += __shfl_down_sync(0xFFFFFFFFu, acc, 16);

    if (lane < 16) {
        float dinv = rsqrtf((float)(cnt + 1));
        float v = (acc + g_feat[(size_t)warp * OUT_DIM + lane]) * dinv
                  + __ldg(&b[lane]);
        out[(size_t)warp * OUT_DIM + lane] = v;
    }
}

// ---------------------------------------------------------------------------
extern "C" void kernel_launch(void* const* d_in, const int* in_sizes, int n_in,
                              void* d_out, int out_size) {
    const float* x  = (const float*)d_in[0];
    const void*  ei = d_in[1];                  // [2, E] int32 OR int64
    const float* W  = (const float*)d_in[2];
    const float* b  = (const float*)d_in[3];
    float* out = (float*)d_out;

    (void)in_sizes; (void)n_in; (void)out_size;

    cudaFuncSetAttribute(gemm_scale_kernel,
                         cudaFuncAttributeMaxDynamicSharedMemorySize,
                         GEMM_SMEM);

    init_kernel<<<(N_NODES + 255) / 256, 256>>>((const int*)ei);        // idx0
    count_kernel<<<(N_EDGES / 4 + 255) / 256, 256>>>(ei);               // idx1
    scan1_kernel<<<NBLK, SB>>>();                                       // idx2
    gemm_scale_kernel<<<(N_NODES + TROWS - 1) / TROWS, GT, GEMM_SMEM>>>(x, W); // idx3 (profiled)
    scan23_kernel<<<NBLK, SB>>>();                                      // idx4
    sort_scatter_kernel<<<(N_EDGES + 255) / 256, 256>>>(ei);            // idx5
    gather_kernel<<<(N_NODES * 32 + 255) / 256, 256>>>(b, out);         // idx6
}